// round 13
// baseline (speedup 1.0000x reference)
#include <cuda_runtime.h>
#include <cuda_fp16.h>
#include <cstdint>

// ---------------- problem constants ----------------
#define N_NODES  50000
#define N_EDGES  800000
#define IN_F     128
#define HEADS    8
#define OUT_F    32
#define HD       256          // HEADS*OUT_F
#define NEXT_PAD 320          // 5 * 64 for GEMM tiling (272 real + pad)
#define NEG_SLOPE 0.2f

// ---------------- device scratch (static, allocation-free) ----------------
// g_count / g_total are zero at module load and re-zeroed by agg_kernel at the
// end of every execution, so no zeroing kernel is needed on the critical path.
__device__ __align__(16) __half g_feat_h[N_NODES * HD];   // 25.6 MB fp16 messages
__device__ float g_el[N_NODES * HEADS];
__device__ float g_er[N_NODES * HEADS];
__device__ float g_wext[NEXT_PAD * IN_F];     // tf32-rounded W rows + al2 + ar2 + pad
__device__ int   g_count[N_NODES];
__device__ int   g_off[N_NODES];
__device__ int   g_epos[N_EDGES];             // rank of edge within its dst bucket
__device__ int   g_total;
__device__ int   g_esrc[N_EDGES];             // src node per edge, grouped by dst

// ---------------- CSR build ----------------
// Histogram that keeps the atomic's return: the rank of edge e within its dst
// bucket. This rank makes the later scatter atomic-free.
__global__ void hist_kernel(const int* __restrict__ dst) {
    int e = blockIdx.x * blockDim.x + threadIdx.x;
    if (e >= N_EDGES) return;
    g_epos[e] = atomicAdd(&g_count[dst[e]], 1);
}

// Segment offsets via warp scan + one atomic per warp. Segment placement is
// order-nondeterministic but per-node sums are unchanged.
__global__ void offsets_kernel() {
    int n    = blockIdx.x * blockDim.x + threadIdx.x;
    int lane = threadIdx.x & 31;
    int c = (n < N_NODES) ? g_count[n] : 0;
    int incl = c;
    #pragma unroll
    for (int d = 1; d < 32; d <<= 1) {
        int v = __shfl_up_sync(0xffffffffu, incl, d);
        if (lane >= d) incl += v;
    }
    int total = __shfl_sync(0xffffffffu, incl, 31);
    int base = 0;
    if (lane == 31) base = atomicAdd(&g_total, total);
    base = __shfl_sync(0xffffffffu, base, 31);
    if (n < N_NODES) g_off[n] = base + incl - c;
}

// Atomic-free scatter: position = off[dst] + rank-from-hist.
__global__ void scatter_kernel(const int* __restrict__ src, const int* __restrict__ dst) {
    int e = blockIdx.x * blockDim.x + threadIdx.x;
    if (e >= N_EDGES) return;
    int d = dst[e];
    g_esrc[g_off[d] + g_epos[e]] = src[e];
}

// ---------------- build extended weight matrix (tf32-rounded) ----------------
__device__ __forceinline__ float cvt_tf32(float x) {
    float y;
    asm("cvt.rna.tf32.f32 %0, %1;" : "=f"(y) : "f"(x));
    return y;
}

__global__ void build_wext_kernel(const float* __restrict__ W,
                                  const float* __restrict__ al,
                                  const float* __restrict__ ar) {
    int idx = blockIdx.x * blockDim.x + threadIdx.x;
    if (idx >= NEXT_PAD * IN_F) return;
    int j = idx / IN_F;
    int k = idx % IN_F;
    float v = 0.0f;
    if (j < HD) {
        v = W[j * IN_F + k];
    } else if (j < HD + HEADS) {
        int h = j - HD;
        float s = 0.0f;
        for (int d = 0; d < OUT_F; d++)
            s += al[h * OUT_F + d] * W[(h * OUT_F + d) * IN_F + k];
        v = s;
    } else if (j < HD + 2 * HEADS) {
        int h = j - HD - HEADS;
        float s = 0.0f;
        for (int d = 0; d < OUT_F; d++)
            s += ar[h * OUT_F + d] * W[(h * OUT_F + d) * IN_F + k];
        v = s;
    }
    g_wext[idx] = cvt_tf32(v);
}

// ---------------- tf32 tensor-core GEMM, cp.async double-buffered ----------------
#define BK   32
#define ASTR 36

__device__ __forceinline__ void cp_async16(uint32_t smem_addr, const void* gptr, int src_bytes) {
    asm volatile("cp.async.ca.shared.global [%0], [%1], 16, %2;\n"
                 :: "r"(smem_addr), "l"(gptr), "r"(src_bytes));
}

__global__ void __launch_bounds__(256, 3) gemm_tf32_kernel(const float* __restrict__ A) {
    extern __shared__ float sh[];
    float* Asb[2] = { sh,                  sh + 128 * ASTR };
    float* Bsb[2] = { sh + 2 * 128 * ASTR, sh + 2 * 128 * ASTR + 64 * ASTR };
    const int bm  = blockIdx.x * 128;
    const int bn  = blockIdx.y * 64;
    const int tid = threadIdx.x;

    uint32_t sA[2], sB[2];
    sA[0] = (uint32_t)__cvta_generic_to_shared(Asb[0]);
    sA[1] = (uint32_t)__cvta_generic_to_shared(Asb[1]);
    sB[0] = (uint32_t)__cvta_generic_to_shared(Bsb[0]);
    sB[1] = (uint32_t)__cvta_generic_to_shared(Bsb[1]);

    const int srow = tid >> 3;
    const int skq  = (tid & 7) << 2;

    auto stage = [&](int buf, int kc) {
        int k0 = kc * BK;
        #pragma unroll
        for (int it = 0; it < 4; it++) {
            int row = srow + it * 32;
            int gr  = bm + row;
            const float* src = A + (size_t)gr * IN_F + k0 + skq;
            cp_async16(sA[buf] + (row * ASTR + skq) * 4, src, gr < N_NODES ? 16 : 0);
        }
        #pragma unroll
        for (int it = 0; it < 2; it++) {
            int row = srow + it * 32;
            const float* src = g_wext + (size_t)(bn + row) * IN_F + k0 + skq;
            cp_async16(sB[buf] + (row * ASTR + skq) * 4, src, 16);
        }
        asm volatile("cp.async.commit_group;\n");
    };

    const int warp = tid >> 5;
    const int lane = tid & 31;
    const int wm = warp >> 1;
    const int wn = warp & 1;
    const int qr = lane >> 2;
    const int qc = lane & 3;

    float acc[2][4][4];
    #pragma unroll
    for (int mt = 0; mt < 2; mt++)
        #pragma unroll
        for (int nt = 0; nt < 4; nt++)
            #pragma unroll
            for (int r = 0; r < 4; r++) acc[mt][nt][r] = 0.f;

    stage(0, 0);

    #pragma unroll
    for (int kc = 0; kc < 4; kc++) {
        int buf = kc & 1;
        if (kc < 3) stage(buf ^ 1, kc + 1);
        if (kc < 3) asm volatile("cp.async.wait_group 1;\n");
        else        asm volatile("cp.async.wait_group 0;\n");
        __syncthreads();

        const float* cAs = Asb[buf];
        const float* cBs = Bsb[buf];
        #pragma unroll
        for (int ks = 0; ks < 4; ks++) {
            int k0 = ks * 8;
            uint32_t a[2][4];
            #pragma unroll
            for (int mt = 0; mt < 2; mt++) {
                const float* p = cAs + (wm * 32 + mt * 16 + qr) * ASTR + k0 + qc;
                a[mt][0] = __float_as_uint(p[0]);
                a[mt][1] = __float_as_uint(p[8 * ASTR]);
                a[mt][2] = __float_as_uint(p[4]);
                a[mt][3] = __float_as_uint(p[8 * ASTR + 4]);
            }
            uint32_t b[4][2];
            #pragma unroll
            for (int nt = 0; nt < 4; nt++) {
                const float* p = cBs + (wn * 32 + nt * 8 + qr) * ASTR + k0 + qc;
                b[nt][0] = __float_as_uint(p[0]);
                b[nt][1] = __float_as_uint(p[4]);
            }
            #pragma unroll
            for (int mt = 0; mt < 2; mt++)
                #pragma unroll
                for (int nt = 0; nt < 4; nt++) {
                    asm volatile(
                        "mma.sync.aligned.m16n8k8.row.col.f32.tf32.tf32.f32 "
                        "{%0,%1,%2,%3}, {%4,%5,%6,%7}, {%8,%9}, {%0,%1,%2,%3};\n"
                        : "+f"(acc[mt][nt][0]), "+f"(acc[mt][nt][1]),
                          "+f"(acc[mt][nt][2]), "+f"(acc[mt][nt][3])
                        : "r"(a[mt][0]), "r"(a[mt][1]), "r"(a[mt][2]), "r"(a[mt][3]),
                          "r"(b[nt][0]), "r"(b[nt][1]));
                }
        }
        __syncthreads();
    }

    // ---- epilogue: fp16 feat_hd + fp32 el/er ----
    #pragma unroll
    for (int mt = 0; mt < 2; mt++) {
        #pragma unroll
        for (int i = 0; i < 2; i++) {
            int row = bm + wm * 32 + mt * 16 + qr + i * 8;
            if (row >= N_NODES) continue;
            #pragma unroll
            for (int nt = 0; nt < 4; nt++) {
                int col = bn + wn * 32 + nt * 8 + 2 * qc;
                float v0 = acc[mt][nt][2 * i];
                float v1 = acc[mt][nt][2 * i + 1];
                if (col < HD) {
                    __half2 hv = __floats2half2_rn(v0, v1);
                    *reinterpret_cast<__half2*>(g_feat_h + (size_t)row * HD + col) = hv;
                } else if (col < HD + HEADS) {
                    *reinterpret_cast<float2*>(g_el + row * HEADS + (col - HD)) =
                        make_float2(v0, v1);
                } else if (col < HD + 2 * HEADS) {
                    *reinterpret_cast<float2*>(g_er + row * HEADS + (col - HD - HEADS)) =
                        make_float2(v0, v1);
                }
            }
        }
    }
}

// ---------------- fused softmax + aggregation: warp per dst node ----------------
// Lane owns uint4 #lane of the 32-uint4 fp16 row = 8 channels; head = lane>>2.
// 2-edge unrolled, strictly in-order accumulation (bit-identical numerics).
// SELF-ZEROING: after consuming g_count[n], lane 0 resets it to 0 (and warp 0
// lane 0 resets g_total), restoring the start-of-execution invariant so the
// next graph replay's hist_kernel needs no separate zeroing kernel.
__global__ void agg_kernel(float* __restrict__ out) {
    int warp = (blockIdx.x * blockDim.x + threadIdx.x) >> 5;
    int lane = threadIdx.x & 31;
    if (warp >= N_NODES) return;
    int n   = warp;
    int p0  = g_off[n];
    int cnt = g_count[n];
    int h   = lane >> 2;
    float er_h = g_er[n * HEADS + h];

    // reset invariant for the next execution (cnt already in a register)
    if (lane == 0) {
        g_count[n] = 0;
        if (n == 0) g_total = 0;
    }

    float acc[8] = {};
    float z = 0.f;
    const uint4* fbase = reinterpret_cast<const uint4*>(g_feat_h);
    int pend = p0 + cnt;
    int p = p0;

    for (; p + 2 <= pend; p += 2) {
        int s0 = g_esrc[p];
        int s1 = g_esrc[p + 1];
        float e0 = g_el[s0 * HEADS + h];
        float e1 = g_el[s1 * HEADS + h];
        uint4 q0 = fbase[(size_t)s0 * (HD / 8) + lane];
        uint4 q1 = fbase[(size_t)s1 * (HD / 8) + lane];

        float x0 = e0 + er_h;
        x0 = fmaxf(x0, NEG_SLOPE * x0);
        float w0 = __expf(x0);
        const __half2* h0 = reinterpret_cast<const __half2*>(&q0);
        #pragma unroll
        for (int j = 0; j < 4; j++) {
            float2 f = __half22float2(h0[j]);
            acc[2 * j]     = fmaf(w0, f.x, acc[2 * j]);
            acc[2 * j + 1] = fmaf(w0, f.y, acc[2 * j + 1]);
        }
        z += w0;

        float x1 = e1 + er_h;
        x1 = fmaxf(x1, NEG_SLOPE * x1);
        float w1 = __expf(x1);
        const __half2* h1 = reinterpret_cast<const __half2*>(&q1);
        #pragma unroll
        for (int j = 0; j < 4; j++) {
            float2 f = __half22float2(h1[j]);
            acc[2 * j]     = fmaf(w1, f.x, acc[2 * j]);
            acc[2 * j + 1] = fmaf(w1, f.y, acc[2 * j + 1]);
        }
        z += w1;
    }
    for (; p < pend; p++) {
        int s = g_esrc[p];
        float x = g_el[s * HEADS + h] + er_h;
        x = fmaxf(x, NEG_SLOPE * x);
        float w = __expf(x);
        uint4 q = fbase[(size_t)s * (HD / 8) + lane];
        const __half2* hh = reinterpret_cast<const __half2*>(&q);
        #pragma unroll
        for (int j = 0; j < 4; j++) {
            float2 f = __half22float2(hh[j]);
            acc[2 * j]     = fmaf(w, f.x, acc[2 * j]);
            acc[2 * j + 1] = fmaf(w, f.y, acc[2 * j + 1]);
        }
        z += w;
    }

    float inv = (cnt > 0) ? (1.0f / z) : 0.f;
    float* orow = out + (size_t)n * HD + lane * 8;
    *reinterpret_cast<float4*>(orow) =
        make_float4(acc[0] * inv, acc[1] * inv, acc[2] * inv, acc[3] * inv);
    *reinterpret_cast<float4*>(orow + 4) =
        make_float4(acc[4] * inv, acc[5] * inv, acc[6] * inv, acc[7] * inv);
}

// ---------------- launch: fork CSR chain (main) and GEMM chain (s2) ----------------
// CSR branch starts directly with hist (counts pre-zeroed: module-load zeros on
// the first call, agg's self-zeroing on every subsequent one). Stream/event
// handles intentionally not destroyed (capture-legal; tiny host-side leak on
// the few non-replay calls).
extern "C" void kernel_launch(void* const* d_in, const int* in_sizes, int n_in,
                              void* d_out, int out_size) {
    const float* feat = (const float*)d_in[0];
    const float* W_fc = (const float*)d_in[1];
    const float* al   = (const float*)d_in[2];
    const float* ar   = (const float*)d_in[3];
    const int*   src  = (const int*)d_in[4];
    const int*   dst  = (const int*)d_in[5];
    float* out = (float*)d_out;

    cudaStream_t s2;
    cudaStreamCreateWithFlags(&s2, cudaStreamNonBlocking);
    cudaEvent_t evFork, evJoin;
    cudaEventCreateWithFlags(&evFork, cudaEventDisableTiming);
    cudaEventCreateWithFlags(&evJoin, cudaEventDisableTiming);

    const int smem_bytes = 2 * (128 + 64) * ASTR * sizeof(float);   // 55296 B
    cudaFuncSetAttribute(gemm_tf32_kernel,
                         cudaFuncAttributeMaxDynamicSharedMemorySize, smem_bytes);

    // fork
    cudaEventRecord(evFork, 0);
    cudaStreamWaitEvent(s2, evFork, 0);

    // branch B (s2): projection GEMM chain
    build_wext_kernel<<<(NEXT_PAD * IN_F + 255) / 256, 256, 0, s2>>>(W_fc, al, ar);
    dim3 ggrid((N_NODES + 127) / 128, NEXT_PAD / 64);
    gemm_tf32_kernel<<<ggrid, 256, smem_bytes, s2>>>(feat);
    cudaEventRecord(evJoin, s2);

    // branch A (main): CSR build chain — no zeroing kernel needed
    hist_kernel<<<(N_EDGES + 255) / 256, 256>>>(dst);
    offsets_kernel<<<(N_NODES + 255) / 256, 256>>>();
    scatter_kernel<<<(N_EDGES + 255) / 256, 256>>>(src, dst);

    // join, then aggregate (self-zeroes counts for the next replay)
    cudaStreamWaitEvent(0, evJoin, 0);
    agg_kernel<<<(N_NODES * 32 + 255) / 256, 256>>>(out);
}

// round 14
// speedup vs baseline: 1.5424x; 1.5424x over previous
#include <cuda_runtime.h>
#include <cuda_fp16.h>
#include <cstdint>

// ---------------- problem constants ----------------
#define N_NODES  50000
#define N_EDGES  800000
#define IN_F     128
#define HEADS    8
#define OUT_F    32
#define HD       256          // HEADS*OUT_F
#define NEXT_PAD 320          // 5 * 64 for GEMM tiling (272 real + pad)
#define NEG_SLOPE 0.2f

// ---------------- device scratch (static, allocation-free) ----------------
__device__ __align__(16) __half g_feat_h[N_NODES * HD];   // 25.6 MB fp16 messages
__device__ float g_el[N_NODES * HEADS];
__device__ float g_er[N_NODES * HEADS];
__device__ float g_wext[NEXT_PAD * IN_F];     // tf32-rounded W rows + al2 + ar2 + pad
__device__ int   g_count[N_NODES];
__device__ int   g_off[N_NODES];
__device__ int   g_epos[N_EDGES];             // rank of edge within its dst bucket
__device__ int   g_total;
__device__ int   g_esrc[N_EDGES];             // src node per edge, grouped by dst

// ---------------- CSR build ----------------
// Dedicated zeroing kernel: also acts as an L2 pre-warm for hist's atomics
// (round 13 showed removing it costs ~55 us, not the predicted -4).
__global__ void zero_counts_kernel() {
    int i = blockIdx.x * blockDim.x + threadIdx.x;
    if (i < N_NODES) g_count[i] = 0;
    if (i == 0) g_total = 0;
}

// Histogram that keeps the atomic's return: the rank of edge e within its dst
// bucket. This rank makes the later scatter atomic-free.
__global__ void hist_kernel(const int* __restrict__ dst) {
    int e = blockIdx.x * blockDim.x + threadIdx.x;
    if (e >= N_EDGES) return;
    g_epos[e] = atomicAdd(&g_count[dst[e]], 1);
}

// Segment offsets via warp scan + one atomic per warp. Segment placement is
// order-nondeterministic but per-node sums are unchanged.
__global__ void offsets_kernel() {
    int n    = blockIdx.x * blockDim.x + threadIdx.x;
    int lane = threadIdx.x & 31;
    int c = (n < N_NODES) ? g_count[n] : 0;
    int incl = c;
    #pragma unroll
    for (int d = 1; d < 32; d <<= 1) {
        int v = __shfl_up_sync(0xffffffffu, incl, d);
        if (lane >= d) incl += v;
    }
    int total = __shfl_sync(0xffffffffu, incl, 31);
    int base = 0;
    if (lane == 31) base = atomicAdd(&g_total, total);
    base = __shfl_sync(0xffffffffu, base, 31);
    if (n < N_NODES) g_off[n] = base + incl - c;
}

// Atomic-free scatter: position = off[dst] + rank-from-hist.
__global__ void scatter_kernel(const int* __restrict__ src, const int* __restrict__ dst) {
    int e = blockIdx.x * blockDim.x + threadIdx.x;
    if (e >= N_EDGES) return;
    int d = dst[e];
    g_esrc[g_off[d] + g_epos[e]] = src[e];
}

// ---------------- build extended weight matrix (tf32-rounded) ----------------
__device__ __forceinline__ float cvt_tf32(float x) {
    float y;
    asm("cvt.rna.tf32.f32 %0, %1;" : "=f"(y) : "f"(x));
    return y;
}

__global__ void build_wext_kernel(const float* __restrict__ W,
                                  const float* __restrict__ al,
                                  const float* __restrict__ ar) {
    int idx = blockIdx.x * blockDim.x + threadIdx.x;
    if (idx >= NEXT_PAD * IN_F) return;
    int j = idx / IN_F;
    int k = idx % IN_F;
    float v = 0.0f;
    if (j < HD) {
        v = W[j * IN_F + k];
    } else if (j < HD + HEADS) {
        int h = j - HD;
        float s = 0.0f;
        for (int d = 0; d < OUT_F; d++)
            s += al[h * OUT_F + d] * W[(h * OUT_F + d) * IN_F + k];
        v = s;
    } else if (j < HD + 2 * HEADS) {
        int h = j - HD - HEADS;
        float s = 0.0f;
        for (int d = 0; d < OUT_F; d++)
            s += ar[h * OUT_F + d] * W[(h * OUT_F + d) * IN_F + k];
        v = s;
    }
    g_wext[idx] = cvt_tf32(v);
}

// ---------------- tf32 tensor-core GEMM, cp.async double-buffered ----------------
#define BK   32
#define ASTR 36

__device__ __forceinline__ void cp_async16(uint32_t smem_addr, const void* gptr, int src_bytes) {
    asm volatile("cp.async.ca.shared.global [%0], [%1], 16, %2;\n"
                 :: "r"(smem_addr), "l"(gptr), "r"(src_bytes));
}

__global__ void __launch_bounds__(256, 3) gemm_tf32_kernel(const float* __restrict__ A) {
    extern __shared__ float sh[];
    float* Asb[2] = { sh,                  sh + 128 * ASTR };
    float* Bsb[2] = { sh + 2 * 128 * ASTR, sh + 2 * 128 * ASTR + 64 * ASTR };
    const int bm  = blockIdx.x * 128;
    const int bn  = blockIdx.y * 64;
    const int tid = threadIdx.x;

    uint32_t sA[2], sB[2];
    sA[0] = (uint32_t)__cvta_generic_to_shared(Asb[0]);
    sA[1] = (uint32_t)__cvta_generic_to_shared(Asb[1]);
    sB[0] = (uint32_t)__cvta_generic_to_shared(Bsb[0]);
    sB[1] = (uint32_t)__cvta_generic_to_shared(Bsb[1]);

    const int srow = tid >> 3;
    const int skq  = (tid & 7) << 2;

    auto stage = [&](int buf, int kc) {
        int k0 = kc * BK;
        #pragma unroll
        for (int it = 0; it < 4; it++) {
            int row = srow + it * 32;
            int gr  = bm + row;
            const float* src = A + (size_t)gr * IN_F + k0 + skq;
            cp_async16(sA[buf] + (row * ASTR + skq) * 4, src, gr < N_NODES ? 16 : 0);
        }
        #pragma unroll
        for (int it = 0; it < 2; it++) {
            int row = srow + it * 32;
            const float* src = g_wext + (size_t)(bn + row) * IN_F + k0 + skq;
            cp_async16(sB[buf] + (row * ASTR + skq) * 4, src, 16);
        }
        asm volatile("cp.async.commit_group;\n");
    };

    const int warp = tid >> 5;
    const int lane = tid & 31;
    const int wm = warp >> 1;
    const int wn = warp & 1;
    const int qr = lane >> 2;
    const int qc = lane & 3;

    float acc[2][4][4];
    #pragma unroll
    for (int mt = 0; mt < 2; mt++)
        #pragma unroll
        for (int nt = 0; nt < 4; nt++)
            #pragma unroll
            for (int r = 0; r < 4; r++) acc[mt][nt][r] = 0.f;

    stage(0, 0);

    #pragma unroll
    for (int kc = 0; kc < 4; kc++) {
        int buf = kc & 1;
        if (kc < 3) stage(buf ^ 1, kc + 1);
        if (kc < 3) asm volatile("cp.async.wait_group 1;\n");
        else        asm volatile("cp.async.wait_group 0;\n");
        __syncthreads();

        const float* cAs = Asb[buf];
        const float* cBs = Bsb[buf];
        #pragma unroll
        for (int ks = 0; ks < 4; ks++) {
            int k0 = ks * 8;
            uint32_t a[2][4];
            #pragma unroll
            for (int mt = 0; mt < 2; mt++) {
                const float* p = cAs + (wm * 32 + mt * 16 + qr) * ASTR + k0 + qc;
                a[mt][0] = __float_as_uint(p[0]);
                a[mt][1] = __float_as_uint(p[8 * ASTR]);
                a[mt][2] = __float_as_uint(p[4]);
                a[mt][3] = __float_as_uint(p[8 * ASTR + 4]);
            }
            uint32_t b[4][2];
            #pragma unroll
            for (int nt = 0; nt < 4; nt++) {
                const float* p = cBs + (wn * 32 + nt * 8 + qr) * ASTR + k0 + qc;
                b[nt][0] = __float_as_uint(p[0]);
                b[nt][1] = __float_as_uint(p[4]);
            }
            #pragma unroll
            for (int mt = 0; mt < 2; mt++)
                #pragma unroll
                for (int nt = 0; nt < 4; nt++) {
                    asm volatile(
                        "mma.sync.aligned.m16n8k8.row.col.f32.tf32.tf32.f32 "
                        "{%0,%1,%2,%3}, {%4,%5,%6,%7}, {%8,%9}, {%0,%1,%2,%3};\n"
                        : "+f"(acc[mt][nt][0]), "+f"(acc[mt][nt][1]),
                          "+f"(acc[mt][nt][2]), "+f"(acc[mt][nt][3])
                        : "r"(a[mt][0]), "r"(a[mt][1]), "r"(a[mt][2]), "r"(a[mt][3]),
                          "r"(b[nt][0]), "r"(b[nt][1]));
                }
        }
        __syncthreads();
    }

    // ---- epilogue: fp16 feat_hd + fp32 el/er ----
    #pragma unroll
    for (int mt = 0; mt < 2; mt++) {
        #pragma unroll
        for (int i = 0; i < 2; i++) {
            int row = bm + wm * 32 + mt * 16 + qr + i * 8;
            if (row >= N_NODES) continue;
            #pragma unroll
            for (int nt = 0; nt < 4; nt++) {
                int col = bn + wn * 32 + nt * 8 + 2 * qc;
                float v0 = acc[mt][nt][2 * i];
                float v1 = acc[mt][nt][2 * i + 1];
                if (col < HD) {
                    __half2 hv = __floats2half2_rn(v0, v1);
                    *reinterpret_cast<__half2*>(g_feat_h + (size_t)row * HD + col) = hv;
                } else if (col < HD + HEADS) {
                    *reinterpret_cast<float2*>(g_el + row * HEADS + (col - HD)) =
                        make_float2(v0, v1);
                } else if (col < HD + 2 * HEADS) {
                    *reinterpret_cast<float2*>(g_er + row * HEADS + (col - HD - HEADS)) =
                        make_float2(v0, v1);
                }
            }
        }
    }
}

// ---------------- fused softmax + aggregation: warp per dst node ----------------
// Lane owns uint4 #lane of the 32-uint4 fp16 row = 8 channels; head = lane>>2
// (8 channels per lane, 32 channels per head -> 4 lanes per head).
// 2-edge unrolled: both edges' esrc/el/rows loaded up front (2x row-load MLP),
// then accumulated IN ORDER (p before p+1) -> numerics bit-identical to the
// scalar loop. (4-edge unroll, 128-thread blocks, prefetch, shfl broadcast,
// and self-zeroing all measured slower across rounds 4-13.)
__global__ void agg_kernel(float* __restrict__ out) {
    int warp = (blockIdx.x * blockDim.x + threadIdx.x) >> 5;
    int lane = threadIdx.x & 31;
    if (warp >= N_NODES) return;
    int n   = warp;
    int p0  = g_off[n];
    int cnt = g_count[n];
    int h   = lane >> 2;
    float er_h = g_er[n * HEADS + h];

    float acc[8] = {};
    float z = 0.f;
    const uint4* fbase = reinterpret_cast<const uint4*>(g_feat_h);
    int pend = p0 + cnt;
    int p = p0;

    for (; p + 2 <= pend; p += 2) {
        int s0 = g_esrc[p];
        int s1 = g_esrc[p + 1];
        float e0 = g_el[s0 * HEADS + h];
        float e1 = g_el[s1 * HEADS + h];
        uint4 q0 = fbase[(size_t)s0 * (HD / 8) + lane];
        uint4 q1 = fbase[(size_t)s1 * (HD / 8) + lane];

        float x0 = e0 + er_h;
        x0 = fmaxf(x0, NEG_SLOPE * x0);
        float w0 = __expf(x0);
        const __half2* h0 = reinterpret_cast<const __half2*>(&q0);
        #pragma unroll
        for (int j = 0; j < 4; j++) {
            float2 f = __half22float2(h0[j]);
            acc[2 * j]     = fmaf(w0, f.x, acc[2 * j]);
            acc[2 * j + 1] = fmaf(w0, f.y, acc[2 * j + 1]);
        }
        z += w0;

        float x1 = e1 + er_h;
        x1 = fmaxf(x1, NEG_SLOPE * x1);
        float w1 = __expf(x1);
        const __half2* h1 = reinterpret_cast<const __half2*>(&q1);
        #pragma unroll
        for (int j = 0; j < 4; j++) {
            float2 f = __half22float2(h1[j]);
            acc[2 * j]     = fmaf(w1, f.x, acc[2 * j]);
            acc[2 * j + 1] = fmaf(w1, f.y, acc[2 * j + 1]);
        }
        z += w1;
    }
    for (; p < pend; p++) {
        int s = g_esrc[p];
        float x = g_el[s * HEADS + h] + er_h;
        x = fmaxf(x, NEG_SLOPE * x);
        float w = __expf(x);
        uint4 q = fbase[(size_t)s * (HD / 8) + lane];
        const __half2* hh = reinterpret_cast<const __half2*>(&q);
        #pragma unroll
        for (int j = 0; j < 4; j++) {
            float2 f = __half22float2(hh[j]);
            acc[2 * j]     = fmaf(w, f.x, acc[2 * j]);
            acc[2 * j + 1] = fmaf(w, f.y, acc[2 * j + 1]);
        }
        z += w;
    }

    float inv = (cnt > 0) ? (1.0f / z) : 0.f;
    float* orow = out + (size_t)n * HD + lane * 8;
    *reinterpret_cast<float4*>(orow) =
        make_float4(acc[0] * inv, acc[1] * inv, acc[2] * inv, acc[3] * inv);
    *reinterpret_cast<float4*>(orow + 4) =
        make_float4(acc[4] * inv, acc[5] * inv, acc[6] * inv, acc[7] * inv);
}

// ---------------- launch: fork CSR chain (main) and GEMM chain (s2) ----------------
// Best-measured configuration (105.95 / 106.14 us, reproduced). Stream/event
// handles intentionally not destroyed (capture-legal; tiny host-side leak on
// the few non-replay calls).
extern "C" void kernel_launch(void* const* d_in, const int* in_sizes, int n_in,
                              void* d_out, int out_size) {
    const float* feat = (const float*)d_in[0];
    const float* W_fc = (const float*)d_in[1];
    const float* al   = (const float*)d_in[2];
    const float* ar   = (const float*)d_in[3];
    const int*   src  = (const int*)d_in[4];
    const int*   dst  = (const int*)d_in[5];
    float* out = (float*)d_out;

    cudaStream_t s2;
    cudaStreamCreateWithFlags(&s2, cudaStreamNonBlocking);
    cudaEvent_t evFork, evJoin;
    cudaEventCreateWithFlags(&evFork, cudaEventDisableTiming);
    cudaEventCreateWithFlags(&evJoin, cudaEventDisableTiming);

    const int smem_bytes = 2 * (128 + 64) * ASTR * sizeof(float);   // 55296 B
    cudaFuncSetAttribute(gemm_tf32_kernel,
                         cudaFuncAttributeMaxDynamicSharedMemorySize, smem_bytes);

    // fork
    cudaEventRecord(evFork, 0);
    cudaStreamWaitEvent(s2, evFork, 0);

    // branch B (s2): projection GEMM chain
    build_wext_kernel<<<(NEXT_PAD * IN_F + 255) / 256, 256, 0, s2>>>(W_fc, al, ar);
    dim3 ggrid((N_NODES + 127) / 128, NEXT_PAD / 64);
    gemm_tf32_kernel<<<ggrid, 256, smem_bytes, s2>>>(feat);
    cudaEventRecord(evJoin, s2);

    // branch A (main): CSR build chain (scatter is atomic-free via epos ranks)
    zero_counts_kernel<<<(N_NODES + 255) / 256, 256>>>();
    hist_kernel<<<(N_EDGES + 255) / 256, 256>>>(dst);
    offsets_kernel<<<(N_NODES + 255) / 256, 256>>>();
    scatter_kernel<<<(N_EDGES + 255) / 256, 256>>>(src, dst);

    // join, then aggregate
    cudaStreamWaitEvent(0, evJoin, 0);
    agg_kernel<<<(N_NODES * 32 + 255) / 256, 256>>>(out);
}